// round 14
// baseline (speedup 1.0000x reference)
#include <cuda_runtime.h>
#include <math.h>

#define NP 8388608          // 32*512*512 pixels
#define HW 262144           // 512*512
#define BSTRIDE 786432      // 3*HW
#define BETA_F 0.15f
#define ODMAX 5.4810        // > -log(1/240)
#define ODNEG 0.0646        // > log(256/240)

// ---------------- device scratch (zero-initialized; every run restores invariants) ---
__device__ double   g_acc[10];
__device__ double   g_emid[3], g_elarge[3];
__device__ float    g_emidf[3], g_elargef[3];
__device__ unsigned g_pfx[2];
__device__ long long g_rank[2];
__device__ float    g_M[6];
__device__ float    g_s[2];
__device__ float    g_kscale[2];
__device__ double   g_kinv[2];
__device__ unsigned g_hist[2][256];
__device__ float    g_od[3ull * NP];       // OD cache fp32, 3 planes (96 MB)
__device__ unsigned short g_keysA[NP];
__device__ unsigned short g_keysB[NP];

// ---------------- helpers ----------------
// OD via MUFU: -log((v+1)/240) = ln2 * (log2(240) - log2(v+1)).
__device__ __forceinline__ float odf(float v) {
    return (7.9068905956085185f - __log2f(v + 1.0f)) * 0.6931471805599453f;
}

// FFMA-only exp(y). Cody-Waite reduction + degree-7 Taylor.
__device__ __forceinline__ float fexp(float y) {
    float z = y * 1.4426950408889634f;
    float n = rintf(z);
    float g = fmaf(n, -0.69314575f, y);
    g = fmaf(n, -1.4286068e-6f, g);
    float r = 1.9841270e-4f;
    r = fmaf(r, g, 1.3888889e-3f);
    r = fmaf(r, g, 8.3333333e-3f);
    r = fmaf(r, g, 4.1666667e-2f);
    r = fmaf(r, g, 1.6666667e-1f);
    r = fmaf(r, g, 0.5f);
    r = fmaf(r, g, 1.0f);
    r = fmaf(r, g, 1.0f);
    int ni = (int)n;
    ni = ni < -126 ? -126 : (ni > 127 ? 127 : ni);
    float s = __int_as_float((unsigned)(ni + 127) << 23);
    return r * s;
}

// warp-aggregated shared-hist add
__device__ __forceinline__ void hadd(unsigned* row, unsigned digit, bool pred) {
    unsigned mm = __ballot_sync(0xffffffffu, pred);
    if (pred) {
        unsigned peers = __match_any_sync(mm, digit);
        int lane = threadIdx.x & 31;
        int leader = __ffs(peers) - 1;
        if (lane == leader) atomicAdd(&row[digit], (unsigned)__popc(peers));
    }
}

// ---------------- 3x3 symmetric Jacobi eigensolver (double) ----------------
__device__ void eig3(double A[3][3], double V[3][3], double w[3]) {
    for (int i = 0; i < 3; i++)
        for (int j = 0; j < 3; j++) V[i][j] = (i == j) ? 1.0 : 0.0;
    const int PQ[3][2] = {{0, 1}, {0, 2}, {1, 2}};
    for (int sweep = 0; sweep < 64; sweep++) {
        double off = A[0][1] * A[0][1] + A[0][2] * A[0][2] + A[1][2] * A[1][2];
        if (off < 1e-300) break;
        for (int r = 0; r < 3; r++) {
            int p = PQ[r][0], q = PQ[r][1];
            double apq = A[p][q];
            if (fabs(apq) < 1e-300) continue;
            double theta = (A[q][q] - A[p][p]) / (2.0 * apq);
            double tt = (theta >= 0.0 ? 1.0 : -1.0) / (fabs(theta) + sqrt(theta * theta + 1.0));
            double c = 1.0 / sqrt(tt * tt + 1.0);
            double s = tt * c;
            double app = A[p][p], aqq = A[q][q];
            A[p][p] = app - tt * apq;
            A[q][q] = aqq + tt * apq;
            A[p][q] = A[q][p] = 0.0;
            int k = 3 - p - q;
            double akp = A[k][p], akq = A[k][q];
            A[k][p] = A[p][k] = c * akp - s * akq;
            A[k][q] = A[q][k] = s * akp + c * akq;
            for (int k2 = 0; k2 < 3; k2++) {
                double vp = V[k2][p], vq = V[k2][q];
                V[k2][p] = c * vp - s * vq;
                V[k2][q] = s * vp + c * vq;
            }
        }
    }
    for (int i = 0; i < 3; i++) w[i] = A[i][i];
    for (int pass = 0; pass < 2; pass++)
        for (int i = 0; i < 2; i++)
            if (w[i] > w[i + 1]) {
                double tw = w[i]; w[i] = w[i + 1]; w[i + 1] = tw;
                for (int k = 0; k < 3; k++) {
                    double tv = V[k][i]; V[k][i] = V[k][i + 1]; V[k][i + 1] = tv;
                }
            }
}

// ---------------- pass 1: fp32 OD cache + masked moments ----------------
__global__ void k_stats(const float* __restrict__ x) {
    float a[10];
#pragma unroll
    for (int i = 0; i < 10; i++) a[i] = 0.0f;
    int tid = blockIdx.x * blockDim.x + threadIdx.x;
    int stride = gridDim.x * blockDim.x;
    for (int q = tid; q < NP / 4; q += stride) {
        int t = q << 2;
        int b = t >> 18, hw = t & (HW - 1);
        const float* p = x + (size_t)b * BSTRIDE + hw;
        float4 v0 = *(const float4*)(p);
        float4 v1 = *(const float4*)(p + HW);
        float4 v2 = *(const float4*)(p + 2 * HW);
        float o0[4] = {odf(v0.x), odf(v0.y), odf(v0.z), odf(v0.w)};
        float o1[4] = {odf(v1.x), odf(v1.y), odf(v1.z), odf(v1.w)};
        float o2[4] = {odf(v2.x), odf(v2.y), odf(v2.z), odf(v2.w)};
        *(float4*)(g_od + t)          = make_float4(o0[0], o0[1], o0[2], o0[3]);
        *(float4*)(g_od + NP + t)     = make_float4(o1[0], o1[1], o1[2], o1[3]);
        *(float4*)(g_od + 2 * NP + t) = make_float4(o2[0], o2[1], o2[2], o2[3]);
#pragma unroll
        for (int j = 0; j < 4; j++) {
            float d0 = o0[j], d1 = o1[j], d2 = o2[j];
            bool keep = !(d0 < BETA_F || d1 < BETA_F || d2 < BETA_F);
            if (keep) {
                a[0] += 1.0f; a[1] += d0; a[2] += d1; a[3] += d2;
                a[4] += d0 * d0; a[5] += d0 * d1; a[6] += d0 * d2;
                a[7] += d1 * d1; a[8] += d1 * d2; a[9] += d2 * d2;
            }
        }
    }
    double d[10];
#pragma unroll
    for (int i = 0; i < 10; i++) d[i] = (double)a[i];
#pragma unroll
    for (int o = 16; o; o >>= 1)
#pragma unroll
        for (int i = 0; i < 10; i++) d[i] += __shfl_down_sync(0xffffffffu, d[i], o);
    __shared__ double sh[8][10];
    int lane = threadIdx.x & 31, w = threadIdx.x >> 5;
    if (lane == 0)
        for (int i = 0; i < 10; i++) sh[w][i] = d[i];
    __syncthreads();
    if (threadIdx.x == 0) {
        for (int ww = 1; ww < (int)(blockDim.x >> 5); ww++)
            for (int i = 0; i < 10; i++) sh[0][i] += sh[ww][i];
        for (int i = 0; i < 10; i++) atomicAdd(&g_acc[i], sh[0][i]);
    }
}

// ---------------- finalize stats -> eigvecs, phi ranks; restore g_acc invariant ----
__global__ void k_finalize1() {
    double n = g_acc[0];
    double mu0 = g_acc[1] / n, mu1 = g_acc[2] / n, mu2 = g_acc[3] / n;
    double inv = 1.0 / (n - 1.0);
    double A[3][3];
    A[0][0] = (g_acc[4] - n * mu0 * mu0) * inv;
    A[0][1] = A[1][0] = (g_acc[5] - n * mu0 * mu1) * inv;
    A[0][2] = A[2][0] = (g_acc[6] - n * mu0 * mu2) * inv;
    A[1][1] = (g_acc[7] - n * mu1 * mu1) * inv;
    A[1][2] = A[2][1] = (g_acc[8] - n * mu1 * mu2) * inv;
    A[2][2] = (g_acc[9] - n * mu2 * mu2) * inv;
    double V[3][3], w[3];
    eig3(A, V, w);
    for (int i = 0; i < 3; i++) {
        g_emid[i] = V[i][1];  g_elarge[i] = V[i][2];
        g_emidf[i] = (float)V[i][1]; g_elargef[i] = (float)V[i][2];
    }
    long long nrej = (long long)NP - (long long)llrint(n);
    double nm1 = n - 1.0;
    g_rank[0] = nrej + llrint(0.01 * 1.0 * nm1);
    g_rank[1] = nrej + llrint(0.01 * 99.0 * nm1);
    g_pfx[0] = 0u; g_pfx[1] = 0u;
    for (int i = 0; i < 10; i++) g_acc[i] = 0.0;
}

// ---------------- pass 2: 16-bit diamond-angle keys + fused high-byte hist ---------
__global__ void k_phi() {
    __shared__ unsigned sh[256];
    for (int i = threadIdx.x; i < 256; i += blockDim.x) sh[i] = 0u;
    __syncthreads();
    float e10 = g_emidf[0], e11 = g_emidf[1], e12 = g_emidf[2];
    float e20 = g_elargef[0], e21 = g_elargef[1], e22 = g_elargef[2];
    int tid = blockIdx.x * blockDim.x + threadIdx.x;
    int stride = gridDim.x * blockDim.x;
    for (int q = tid; q < NP / 4; q += stride) {
        int t = q << 2;
        float4 o0 = *(const float4*)(g_od + t);
        float4 o1 = *(const float4*)(g_od + NP + t);
        float4 o2 = *(const float4*)(g_od + 2 * NP + t);
        float a0[4] = {o0.x, o0.y, o0.z, o0.w};
        float a1[4] = {o1.x, o1.y, o1.z, o1.w};
        float a2[4] = {o2.x, o2.y, o2.z, o2.w};
        unsigned keys[4];
#pragma unroll
        for (int j = 0; j < 4; j++) {
            bool keep = !(a0[j] < BETA_F || a1[j] < BETA_F || a2[j] < BETA_F);
            unsigned key = 0u;
            if (keep) {
                float t1 = fmaf(a2[j], e12, fmaf(a1[j], e11, a0[j] * e10));
                float t2 = fmaf(a2[j], e22, fmaf(a1[j], e21, a0[j] * e20));
                float s = fabsf(t1) + fabsf(t2);
                float p = copysignf(1.0f - __fdividef(t1, s), t2);  // diamond angle
                float kf = fmaf(p, 16383.75f, 32767.5f);
                kf = fminf(fmaxf(kf, 0.0f), 65535.0f);
                key = (unsigned)kf;
            }
            keys[j] = key;
            hadd(sh, key >> 8, true);
        }
        ushort4 kv;
        kv.x = (unsigned short)keys[0]; kv.y = (unsigned short)keys[1];
        kv.z = (unsigned short)keys[2]; kv.w = (unsigned short)keys[3];
        *(ushort4*)(g_keysA + t) = kv;
    }
    __syncthreads();
    for (int i = threadIdx.x; i < 256; i += blockDim.x) {
        unsigned c = sh[i];
        if (c) { atomicAdd(&g_hist[0][i], c); atomicAdd(&g_hist[1][i], c); }
    }
}

// ---------------- low-byte histogram pass over 16-bit keys ----------------
__global__ void k_hist2(int useB) {
    __shared__ unsigned sh[2][256];
    for (int i = threadIdx.x; i < 512; i += blockDim.x) ((unsigned*)sh)[i] = 0u;
    __syncthreads();
    unsigned p0 = g_pfx[0], p1 = g_pfx[1];
    int tid = blockIdx.x * blockDim.x + threadIdx.x;
    int stride = gridDim.x * blockDim.x;
    for (int q = tid; q < NP / 8; q += stride) {
        uint4 va = ((const uint4*)g_keysA)[q];
        unsigned ka[8] = {va.x & 0xFFFFu, va.x >> 16, va.y & 0xFFFFu, va.y >> 16,
                          va.z & 0xFFFFu, va.z >> 16, va.w & 0xFFFFu, va.w >> 16};
        if (useB) {
            uint4 vb = ((const uint4*)g_keysB)[q];
            unsigned kb[8] = {vb.x & 0xFFFFu, vb.x >> 16, vb.y & 0xFFFFu, vb.y >> 16,
                              vb.z & 0xFFFFu, vb.z >> 16, vb.w & 0xFFFFu, vb.w >> 16};
#pragma unroll
            for (int j = 0; j < 8; j++) {
                hadd(sh[0], ka[j] & 255u, (ka[j] >> 8) == p0);
                hadd(sh[1], kb[j] & 255u, (kb[j] >> 8) == p1);
            }
        } else {
#pragma unroll
            for (int j = 0; j < 8; j++) {
                hadd(sh[0], ka[j] & 255u, (ka[j] >> 8) == p0);
                hadd(sh[1], ka[j] & 255u, (ka[j] >> 8) == p1);
            }
        }
    }
    __syncthreads();
    for (int i = threadIdx.x; i < 256; i += blockDim.x) {
        if (sh[0][i]) atomicAdd(&g_hist[0][i], sh[0][i]);
        if (sh[1][i]) atomicAdd(&g_hist[1][i], sh[1][i]);
    }
}

// ---------------- select + staged finalize ----------------
__global__ void k_select(int stage) {
    int tsel = threadIdx.x >> 5;
    int lane = threadIdx.x & 31;
    long long r = g_rank[tsel];
    unsigned run = 0u; int found = -1; unsigned before = 0u;
    for (int base = 0; base < 256; base += 32) {
        unsigned c = g_hist[tsel][base + lane];
        unsigned inc = c;
#pragma unroll
        for (int o = 1; o < 32; o <<= 1) {
            unsigned v = __shfl_up_sync(0xffffffffu, inc, o);
            if (lane >= o) inc += v;
        }
        unsigned tot = __shfl_sync(0xffffffffu, inc, 31);
        if (found < 0) {
            long long excl = (long long)run + (long long)(inc - c);
            long long cum  = (long long)run + (long long)inc;
            bool hit = (excl <= r) && (cum > r);
            unsigned hm = __ballot_sync(0xffffffffu, hit);
            if (hm) {
                int hl = __ffs(hm) - 1;
                found = base + hl;
                before = run + __shfl_sync(0xffffffffu, inc - c, hl);
            }
        }
        run += tot;
        g_hist[tsel][base + lane] = 0u;
    }
    if (lane == 0) {
        g_pfx[tsel] = (g_pfx[tsel] << 8) | (unsigned)found;
        g_rank[tsel] = r - (long long)before;
    }
    __syncthreads();
    if (threadIdx.x == 0) {
        if (stage == 1) {
            double ph[2];
            for (int t = 0; t < 2; t++) {
                double p = ((double)g_pfx[t] + 0.5) / 16383.75 - 2.0;
                double ap = fabs(p);
                double xx = 1.0 - ap;
                double yy = (1.0 - fabs(1.0 - ap)); yy = (p < 0.0) ? -yy : yy;
                ph[t] = atan2(yy, xx);
            }
            double vMin[3], vMax[3];
            double cmin = cos(ph[0]), smin = sin(ph[0]);
            double cmax = cos(ph[1]), smax = sin(ph[1]);
            for (int i = 0; i < 3; i++) {
                vMin[i] = cmin * g_emid[i] + smin * g_elarge[i];
                vMax[i] = cmax * g_emid[i] + smax * g_elarge[i];
            }
            double h1[3], h2[3];
            if (vMin[0] > vMax[0]) {
                for (int i = 0; i < 3; i++) { h1[i] = vMin[i]; h2[i] = vMax[i]; }
            } else {
                for (int i = 0; i < 3; i++) { h1[i] = vMax[i]; h2[i] = vMin[i]; }
            }
            double a = h1[0]*h1[0] + h1[1]*h1[1] + h1[2]*h1[2];
            double b = h1[0]*h2[0] + h1[1]*h2[1] + h1[2]*h2[2];
            double d = h2[0]*h2[0] + h2[1]*h2[1] + h2[2]*h2[2];
            double det = a * d - b * b;
            double M[6];
            for (int i = 0; i < 3; i++) {
                M[i]     = (d * h1[i] - b * h2[i]) / det;
                M[3 + i] = (a * h2[i] - b * h1[i]) / det;
            }
            for (int i = 0; i < 6; i++) g_M[i] = (float)M[i];
            for (int t = 0; t < 2; t++) {
                double R = 0.0;
                for (int i = 0; i < 3; i++) {
                    double m = M[3 * t + i];
                    R += (m > 0.0) ? m * ODMAX : -m * ODNEG;
                }
                R = R * 1.001 + 1e-6;
                g_kscale[t] = (float)(65535.0 / R);
                g_kinv[t] = R / 65535.0;
            }
            long long r99 = llrint(0.01 * 99.0 * (double)(NP - 1));
            g_rank[0] = r99; g_rank[1] = r99;
            g_pfx[0] = 0u; g_pfx[1] = 0u;
        } else if (stage == 2) {
            g_s[0] = (float)(1.9705 / (((double)g_pfx[0] + 0.5) * g_kinv[0]));
            g_s[1] = (float)(1.0308 / (((double)g_pfx[1] + 0.5) * g_kinv[1]));
        }
    }
}

// ---------------- pass 3a: C0 keys + single high-byte hist (phi-clone shape) -------
__global__ void k_cmatA() {
    __shared__ unsigned sh[256];
    for (int i = threadIdx.x; i < 256; i += blockDim.x) sh[i] = 0u;
    __syncthreads();
    float m0 = g_M[0], m1 = g_M[1], m2 = g_M[2];
    float s0 = g_kscale[0];
    int tid = blockIdx.x * blockDim.x + threadIdx.x;
    int stride = gridDim.x * blockDim.x;
    for (int q = tid; q < NP / 4; q += stride) {
        int t = q << 2;
        float4 o0 = *(const float4*)(g_od + t);
        float4 o1 = *(const float4*)(g_od + NP + t);
        float4 o2 = *(const float4*)(g_od + 2 * NP + t);
        float a0[4] = {o0.x, o0.y, o0.z, o0.w};
        float a1[4] = {o1.x, o1.y, o1.z, o1.w};
        float a2[4] = {o2.x, o2.y, o2.z, o2.w};
        unsigned kA[4];
#pragma unroll
        for (int j = 0; j < 4; j++) {
            float c0 = fmaf(a2[j], m2, fmaf(a1[j], m1, a0[j] * m0));
            float f0 = fminf(fmaxf(c0 * s0, 0.0f), 65535.0f);
            kA[j] = (unsigned)f0;
            hadd(sh, kA[j] >> 8, true);
        }
        ushort4 va;
        va.x = (unsigned short)kA[0]; va.y = (unsigned short)kA[1];
        va.z = (unsigned short)kA[2]; va.w = (unsigned short)kA[3];
        *(ushort4*)(g_keysA + t) = va;
    }
    __syncthreads();
    for (int i = threadIdx.x; i < 256; i += blockDim.x) {
        unsigned c = sh[i];
        if (c) atomicAdd(&g_hist[0][i], c);
    }
}

// ---------------- pass 3b: C1 keys + single high-byte hist (phi-clone shape) -------
__global__ void k_cmatB() {
    __shared__ unsigned sh[256];
    for (int i = threadIdx.x; i < 256; i += blockDim.x) sh[i] = 0u;
    __syncthreads();
    float m3 = g_M[3], m4 = g_M[4], m5 = g_M[5];
    float s1 = g_kscale[1];
    int tid = blockIdx.x * blockDim.x + threadIdx.x;
    int stride = gridDim.x * blockDim.x;
    for (int q = tid; q < NP / 4; q += stride) {
        int t = q << 2;
        float4 o0 = *(const float4*)(g_od + t);
        float4 o1 = *(const float4*)(g_od + NP + t);
        float4 o2 = *(const float4*)(g_od + 2 * NP + t);
        float a0[4] = {o0.x, o0.y, o0.z, o0.w};
        float a1[4] = {o1.x, o1.y, o1.z, o1.w};
        float a2[4] = {o2.x, o2.y, o2.z, o2.w};
        unsigned kB[4];
#pragma unroll
        for (int j = 0; j < 4; j++) {
            float c1 = fmaf(a2[j], m5, fmaf(a1[j], m4, a0[j] * m3));
            float f1 = fminf(fmaxf(c1 * s1, 0.0f), 65535.0f);
            kB[j] = (unsigned)f1;
            hadd(sh, kB[j] >> 8, true);
        }
        ushort4 vb;
        vb.x = (unsigned short)kB[0]; vb.y = (unsigned short)kB[1];
        vb.z = (unsigned short)kB[2]; vb.w = (unsigned short)kB[3];
        *(ushort4*)(g_keysB + t) = vb;
    }
    __syncthreads();
    for (int i = threadIdx.x; i < 256; i += blockDim.x) {
        unsigned c = sh[i];
        if (c) atomicAdd(&g_hist[1][i], c);
    }
}

// ---------------- pass 4: normalized output from fp32 OD cache ----------------
__global__ void k_out(float* __restrict__ out) {
    float m0 = g_M[0], m1 = g_M[1], m2 = g_M[2];
    float m3 = g_M[3], m4 = g_M[4], m5 = g_M[5];
    float s0 = g_s[0], s1 = g_s[1];
    int tid = blockIdx.x * blockDim.x + threadIdx.x;
    int stride = gridDim.x * blockDim.x;
    for (int q = tid; q < NP / 4; q += stride) {
        int t = q << 2;
        float4 o0 = *(const float4*)(g_od + t);
        float4 o1 = *(const float4*)(g_od + NP + t);
        float4 o2 = *(const float4*)(g_od + 2 * NP + t);
        float a0[4] = {o0.x, o0.y, o0.z, o0.w};
        float a1[4] = {o1.x, o1.y, o1.z, o1.w};
        float a2[4] = {o2.x, o2.y, o2.z, o2.w};
        float r0[4], r1[4], r2[4];
#pragma unroll
        for (int j = 0; j < 4; j++) {
            float c0 = fmaf(a2[j], m2, fmaf(a1[j], m1, a0[j] * m0)) * s0;
            float c1 = fmaf(a2[j], m5, fmaf(a1[j], m4, a0[j] * m3)) * s1;
            r0[j] = fminf(240.0f * fexp(-fmaf(0.5626f, c0, 0.2159f * c1)), 255.0f);
            r1[j] = fminf(240.0f * fexp(-fmaf(0.7201f, c0, 0.8012f * c1)), 255.0f);
            r2[j] = fminf(240.0f * fexp(-fmaf(0.4062f, c0, 0.5581f * c1)), 255.0f);
        }
        int b = t >> 18, hw = t & (HW - 1);
        float* o = out + (size_t)b * BSTRIDE + hw;
        *(float4*)(o)          = make_float4(r0[0], r0[1], r0[2], r0[3]);
        *(float4*)(o + HW)     = make_float4(r1[0], r1[1], r1[2], r1[3]);
        *(float4*)(o + 2 * HW) = make_float4(r2[0], r2[1], r2[2], r2[3]);
    }
}

// ---------------- launch (12 kernels; champion + split cmat) ----------------
extern "C" void kernel_launch(void* const* d_in, const int* in_sizes, int n_in,
                              void* d_out, int out_size) {
    const float* x = (const float*)d_in[0];
    float* out = (float*)d_out;
    const int TB = 256;
    const int GB = 2048;

    k_stats<<<GB, TB>>>(x);
    k_finalize1<<<1, 1>>>();
    k_phi<<<GB, TB>>>();
    k_select<<<1, 64>>>(0);
    k_hist2<<<GB, TB>>>(0);
    k_select<<<1, 64>>>(1);
    k_cmatA<<<GB, TB>>>();
    k_cmatB<<<GB, TB>>>();
    k_select<<<1, 64>>>(0);
    k_hist2<<<GB, TB>>>(1);
    k_select<<<1, 64>>>(2);
    k_out<<<GB, TB>>>(out);
}

// round 15
// speedup vs baseline: 1.4888x; 1.4888x over previous
#include <cuda_runtime.h>
#include <math.h>

#define NP 8388608          // 32*512*512 pixels
#define HW 262144           // 512*512
#define BSTRIDE 786432      // 3*HW
#define BETA_F 0.15f
#define ODMAX 5.4810        // > -log(1/240)
#define ODNEG 0.0646        // > log(256/240)

// ---------------- device scratch (zero-initialized; every run restores invariants) ---
__device__ double   g_acc[10];
__device__ double   g_emid[3], g_elarge[3];
__device__ float    g_emidf[3], g_elargef[3];
__device__ unsigned g_pfx[2];
__device__ long long g_rank[2];
__device__ float    g_M[6];
__device__ float    g_s[2];
__device__ float    g_kscale[2];
__device__ double   g_kinv[2];
__device__ unsigned g_hist[2][256];
__device__ float    g_od[3ull * NP];       // OD cache fp32, 3 planes (96 MB)
__device__ unsigned short g_keysA[NP];
__device__ unsigned short g_keysB[NP];

// ---------------- helpers ----------------
// OD via MUFU: -log((v+1)/240) = ln2 * (log2(240) - log2(v+1)).
__device__ __forceinline__ float odf(float v) {
    return (7.9068905956085185f - __log2f(v + 1.0f)) * 0.6931471805599453f;
}

// FFMA-only exp(y). Cody-Waite reduction + degree-7 Taylor.
__device__ __forceinline__ float fexp(float y) {
    float z = y * 1.4426950408889634f;
    float n = rintf(z);
    float g = fmaf(n, -0.69314575f, y);
    g = fmaf(n, -1.4286068e-6f, g);
    float r = 1.9841270e-4f;
    r = fmaf(r, g, 1.3888889e-3f);
    r = fmaf(r, g, 8.3333333e-3f);
    r = fmaf(r, g, 4.1666667e-2f);
    r = fmaf(r, g, 1.6666667e-1f);
    r = fmaf(r, g, 0.5f);
    r = fmaf(r, g, 1.0f);
    r = fmaf(r, g, 1.0f);
    int ni = (int)n;
    ni = ni < -126 ? -126 : (ni > 127 ? 127 : ni);
    float s = __int_as_float((unsigned)(ni + 127) << 23);
    return r * s;
}

// deposit WITHOUT match_any: hot bin 0 aggregated via ballot+popc (one atomic/warp);
// all other digits use a plain per-thread shared atomic (spread -> low conflict).
__device__ __forceinline__ void padd(unsigned* row, unsigned digit) {
    unsigned zb = __ballot_sync(0xffffffffu, digit == 0u);
    if (digit == 0u) {
        if ((threadIdx.x & 31u) == (unsigned)(__ffs(zb) - 1))
            atomicAdd(&row[0], (unsigned)__popc(zb));
    } else {
        atomicAdd(&row[digit], 1u);
    }
}

// predicated warp-aggregated add (kept ONLY for k_hist2's rare deposits)
__device__ __forceinline__ void hadd(unsigned* row, unsigned digit, bool pred) {
    unsigned mm = __ballot_sync(0xffffffffu, pred);
    if (pred) {
        unsigned peers = __match_any_sync(mm, digit);
        int lane = threadIdx.x & 31;
        int leader = __ffs(peers) - 1;
        if (lane == leader) atomicAdd(&row[digit], (unsigned)__popc(peers));
    }
}

// ---------------- 3x3 symmetric Jacobi eigensolver (double) ----------------
__device__ void eig3(double A[3][3], double V[3][3], double w[3]) {
    for (int i = 0; i < 3; i++)
        for (int j = 0; j < 3; j++) V[i][j] = (i == j) ? 1.0 : 0.0;
    const int PQ[3][2] = {{0, 1}, {0, 2}, {1, 2}};
    for (int sweep = 0; sweep < 64; sweep++) {
        double off = A[0][1] * A[0][1] + A[0][2] * A[0][2] + A[1][2] * A[1][2];
        if (off < 1e-300) break;
        for (int r = 0; r < 3; r++) {
            int p = PQ[r][0], q = PQ[r][1];
            double apq = A[p][q];
            if (fabs(apq) < 1e-300) continue;
            double theta = (A[q][q] - A[p][p]) / (2.0 * apq);
            double tt = (theta >= 0.0 ? 1.0 : -1.0) / (fabs(theta) + sqrt(theta * theta + 1.0));
            double c = 1.0 / sqrt(tt * tt + 1.0);
            double s = tt * c;
            double app = A[p][p], aqq = A[q][q];
            A[p][p] = app - tt * apq;
            A[q][q] = aqq + tt * apq;
            A[p][q] = A[q][p] = 0.0;
            int k = 3 - p - q;
            double akp = A[k][p], akq = A[k][q];
            A[k][p] = A[p][k] = c * akp - s * akq;
            A[k][q] = A[q][k] = s * akp + c * akq;
            for (int k2 = 0; k2 < 3; k2++) {
                double vp = V[k2][p], vq = V[k2][q];
                V[k2][p] = c * vp - s * vq;
                V[k2][q] = s * vp + c * vq;
            }
        }
    }
    for (int i = 0; i < 3; i++) w[i] = A[i][i];
    for (int pass = 0; pass < 2; pass++)
        for (int i = 0; i < 2; i++)
            if (w[i] > w[i + 1]) {
                double tw = w[i]; w[i] = w[i + 1]; w[i + 1] = tw;
                for (int k = 0; k < 3; k++) {
                    double tv = V[k][i]; V[k][i] = V[k][i + 1]; V[k][i + 1] = tv;
                }
            }
}

// ---------------- pass 1: fp32 OD cache + masked moments ----------------
__global__ void k_stats(const float* __restrict__ x) {
    float a[10];
#pragma unroll
    for (int i = 0; i < 10; i++) a[i] = 0.0f;
    int tid = blockIdx.x * blockDim.x + threadIdx.x;
    int stride = gridDim.x * blockDim.x;
    for (int q = tid; q < NP / 4; q += stride) {
        int t = q << 2;
        int b = t >> 18, hw = t & (HW - 1);
        const float* p = x + (size_t)b * BSTRIDE + hw;
        float4 v0 = *(const float4*)(p);
        float4 v1 = *(const float4*)(p + HW);
        float4 v2 = *(const float4*)(p + 2 * HW);
        float o0[4] = {odf(v0.x), odf(v0.y), odf(v0.z), odf(v0.w)};
        float o1[4] = {odf(v1.x), odf(v1.y), odf(v1.z), odf(v1.w)};
        float o2[4] = {odf(v2.x), odf(v2.y), odf(v2.z), odf(v2.w)};
        *(float4*)(g_od + t)          = make_float4(o0[0], o0[1], o0[2], o0[3]);
        *(float4*)(g_od + NP + t)     = make_float4(o1[0], o1[1], o1[2], o1[3]);
        *(float4*)(g_od + 2 * NP + t) = make_float4(o2[0], o2[1], o2[2], o2[3]);
#pragma unroll
        for (int j = 0; j < 4; j++) {
            float d0 = o0[j], d1 = o1[j], d2 = o2[j];
            bool keep = !(d0 < BETA_F || d1 < BETA_F || d2 < BETA_F);
            if (keep) {
                a[0] += 1.0f; a[1] += d0; a[2] += d1; a[3] += d2;
                a[4] += d0 * d0; a[5] += d0 * d1; a[6] += d0 * d2;
                a[7] += d1 * d1; a[8] += d1 * d2; a[9] += d2 * d2;
            }
        }
    }
    double d[10];
#pragma unroll
    for (int i = 0; i < 10; i++) d[i] = (double)a[i];
#pragma unroll
    for (int o = 16; o; o >>= 1)
#pragma unroll
        for (int i = 0; i < 10; i++) d[i] += __shfl_down_sync(0xffffffffu, d[i], o);
    __shared__ double sh[8][10];
    int lane = threadIdx.x & 31, w = threadIdx.x >> 5;
    if (lane == 0)
        for (int i = 0; i < 10; i++) sh[w][i] = d[i];
    __syncthreads();
    if (threadIdx.x == 0) {
        for (int ww = 1; ww < (int)(blockDim.x >> 5); ww++)
            for (int i = 0; i < 10; i++) sh[0][i] += sh[ww][i];
        for (int i = 0; i < 10; i++) atomicAdd(&g_acc[i], sh[0][i]);
    }
}

// ---------------- finalize stats -> eigvecs, phi ranks; restore g_acc invariant ----
__global__ void k_finalize1() {
    double n = g_acc[0];
    double mu0 = g_acc[1] / n, mu1 = g_acc[2] / n, mu2 = g_acc[3] / n;
    double inv = 1.0 / (n - 1.0);
    double A[3][3];
    A[0][0] = (g_acc[4] - n * mu0 * mu0) * inv;
    A[0][1] = A[1][0] = (g_acc[5] - n * mu0 * mu1) * inv;
    A[0][2] = A[2][0] = (g_acc[6] - n * mu0 * mu2) * inv;
    A[1][1] = (g_acc[7] - n * mu1 * mu1) * inv;
    A[1][2] = A[2][1] = (g_acc[8] - n * mu1 * mu2) * inv;
    A[2][2] = (g_acc[9] - n * mu2 * mu2) * inv;
    double V[3][3], w[3];
    eig3(A, V, w);
    for (int i = 0; i < 3; i++) {
        g_emid[i] = V[i][1];  g_elarge[i] = V[i][2];
        g_emidf[i] = (float)V[i][1]; g_elargef[i] = (float)V[i][2];
    }
    long long nrej = (long long)NP - (long long)llrint(n);
    double nm1 = n - 1.0;
    g_rank[0] = nrej + llrint(0.01 * 1.0 * nm1);
    g_rank[1] = nrej + llrint(0.01 * 99.0 * nm1);
    g_pfx[0] = 0u; g_pfx[1] = 0u;
    for (int i = 0; i < 10; i++) g_acc[i] = 0.0;
}

// ---------------- pass 2: 16-bit diamond-angle keys + plain-atomic hist ------------
__global__ void k_phi() {
    __shared__ unsigned sh[256];
    for (int i = threadIdx.x; i < 256; i += blockDim.x) sh[i] = 0u;
    __syncthreads();
    float e10 = g_emidf[0], e11 = g_emidf[1], e12 = g_emidf[2];
    float e20 = g_elargef[0], e21 = g_elargef[1], e22 = g_elargef[2];
    int tid = blockIdx.x * blockDim.x + threadIdx.x;
    int stride = gridDim.x * blockDim.x;
    for (int q = tid; q < NP / 4; q += stride) {
        int t = q << 2;
        float4 o0 = *(const float4*)(g_od + t);
        float4 o1 = *(const float4*)(g_od + NP + t);
        float4 o2 = *(const float4*)(g_od + 2 * NP + t);
        float a0[4] = {o0.x, o0.y, o0.z, o0.w};
        float a1[4] = {o1.x, o1.y, o1.z, o1.w};
        float a2[4] = {o2.x, o2.y, o2.z, o2.w};
        unsigned keys[4];
#pragma unroll
        for (int j = 0; j < 4; j++) {
            bool keep = !(a0[j] < BETA_F || a1[j] < BETA_F || a2[j] < BETA_F);
            unsigned key = 0u;
            if (keep) {
                float t1 = fmaf(a2[j], e12, fmaf(a1[j], e11, a0[j] * e10));
                float t2 = fmaf(a2[j], e22, fmaf(a1[j], e21, a0[j] * e20));
                float s = fabsf(t1) + fabsf(t2);
                float p = copysignf(1.0f - __fdividef(t1, s), t2);  // diamond angle
                float kf = fmaf(p, 16383.75f, 32767.5f);
                kf = fminf(fmaxf(kf, 0.0f), 65535.0f);
                key = (unsigned)kf;
            }
            keys[j] = key;
            padd(sh, key >> 8);
        }
        ushort4 kv;
        kv.x = (unsigned short)keys[0]; kv.y = (unsigned short)keys[1];
        kv.z = (unsigned short)keys[2]; kv.w = (unsigned short)keys[3];
        *(ushort4*)(g_keysA + t) = kv;
    }
    __syncthreads();
    for (int i = threadIdx.x; i < 256; i += blockDim.x) {
        unsigned c = sh[i];
        if (c) { atomicAdd(&g_hist[0][i], c); atomicAdd(&g_hist[1][i], c); }
    }
}

// ---------------- low-byte histogram pass over 16-bit keys (rare deposits) ---------
__global__ void k_hist2(int useB) {
    __shared__ unsigned sh[2][256];
    for (int i = threadIdx.x; i < 512; i += blockDim.x) ((unsigned*)sh)[i] = 0u;
    __syncthreads();
    unsigned p0 = g_pfx[0], p1 = g_pfx[1];
    int tid = blockIdx.x * blockDim.x + threadIdx.x;
    int stride = gridDim.x * blockDim.x;
    for (int q = tid; q < NP / 8; q += stride) {
        uint4 va = ((const uint4*)g_keysA)[q];
        unsigned ka[8] = {va.x & 0xFFFFu, va.x >> 16, va.y & 0xFFFFu, va.y >> 16,
                          va.z & 0xFFFFu, va.z >> 16, va.w & 0xFFFFu, va.w >> 16};
        if (useB) {
            uint4 vb = ((const uint4*)g_keysB)[q];
            unsigned kb[8] = {vb.x & 0xFFFFu, vb.x >> 16, vb.y & 0xFFFFu, vb.y >> 16,
                              vb.z & 0xFFFFu, vb.z >> 16, vb.w & 0xFFFFu, vb.w >> 16};
#pragma unroll
            for (int j = 0; j < 8; j++) {
                hadd(sh[0], ka[j] & 255u, (ka[j] >> 8) == p0);
                hadd(sh[1], kb[j] & 255u, (kb[j] >> 8) == p1);
            }
        } else {
#pragma unroll
            for (int j = 0; j < 8; j++) {
                hadd(sh[0], ka[j] & 255u, (ka[j] >> 8) == p0);
                hadd(sh[1], ka[j] & 255u, (ka[j] >> 8) == p1);
            }
        }
    }
    __syncthreads();
    for (int i = threadIdx.x; i < 256; i += blockDim.x) {
        if (sh[0][i]) atomicAdd(&g_hist[0][i], sh[0][i]);
        if (sh[1][i]) atomicAdd(&g_hist[1][i], sh[1][i]);
    }
}

// ---------------- select + staged finalize ----------------
__global__ void k_select(int stage) {
    int tsel = threadIdx.x >> 5;
    int lane = threadIdx.x & 31;
    long long r = g_rank[tsel];
    unsigned run = 0u; int found = -1; unsigned before = 0u;
    for (int base = 0; base < 256; base += 32) {
        unsigned c = g_hist[tsel][base + lane];
        unsigned inc = c;
#pragma unroll
        for (int o = 1; o < 32; o <<= 1) {
            unsigned v = __shfl_up_sync(0xffffffffu, inc, o);
            if (lane >= o) inc += v;
        }
        unsigned tot = __shfl_sync(0xffffffffu, inc, 31);
        if (found < 0) {
            long long excl = (long long)run + (long long)(inc - c);
            long long cum  = (long long)run + (long long)inc;
            bool hit = (excl <= r) && (cum > r);
            unsigned hm = __ballot_sync(0xffffffffu, hit);
            if (hm) {
                int hl = __ffs(hm) - 1;
                found = base + hl;
                before = run + __shfl_sync(0xffffffffu, inc - c, hl);
            }
        }
        run += tot;
        g_hist[tsel][base + lane] = 0u;
    }
    if (lane == 0) {
        g_pfx[tsel] = (g_pfx[tsel] << 8) | (unsigned)found;
        g_rank[tsel] = r - (long long)before;
    }
    __syncthreads();
    if (threadIdx.x == 0) {
        if (stage == 1) {
            double ph[2];
            for (int t = 0; t < 2; t++) {
                double p = ((double)g_pfx[t] + 0.5) / 16383.75 - 2.0;
                double ap = fabs(p);
                double xx = 1.0 - ap;
                double yy = (1.0 - fabs(1.0 - ap)); yy = (p < 0.0) ? -yy : yy;
                ph[t] = atan2(yy, xx);
            }
            double vMin[3], vMax[3];
            double cmin = cos(ph[0]), smin = sin(ph[0]);
            double cmax = cos(ph[1]), smax = sin(ph[1]);
            for (int i = 0; i < 3; i++) {
                vMin[i] = cmin * g_emid[i] + smin * g_elarge[i];
                vMax[i] = cmax * g_emid[i] + smax * g_elarge[i];
            }
            double h1[3], h2[3];
            if (vMin[0] > vMax[0]) {
                for (int i = 0; i < 3; i++) { h1[i] = vMin[i]; h2[i] = vMax[i]; }
            } else {
                for (int i = 0; i < 3; i++) { h1[i] = vMax[i]; h2[i] = vMin[i]; }
            }
            double a = h1[0]*h1[0] + h1[1]*h1[1] + h1[2]*h1[2];
            double b = h1[0]*h2[0] + h1[1]*h2[1] + h1[2]*h2[2];
            double d = h2[0]*h2[0] + h2[1]*h2[1] + h2[2]*h2[2];
            double det = a * d - b * b;
            double M[6];
            for (int i = 0; i < 3; i++) {
                M[i]     = (d * h1[i] - b * h2[i]) / det;
                M[3 + i] = (a * h2[i] - b * h1[i]) / det;
            }
            for (int i = 0; i < 6; i++) g_M[i] = (float)M[i];
            for (int t = 0; t < 2; t++) {
                double R = 0.0;
                for (int i = 0; i < 3; i++) {
                    double m = M[3 * t + i];
                    R += (m > 0.0) ? m * ODMAX : -m * ODNEG;
                }
                R = R * 1.001 + 1e-6;
                g_kscale[t] = (float)(65535.0 / R);
                g_kinv[t] = R / 65535.0;
            }
            long long r99 = llrint(0.01 * 99.0 * (double)(NP - 1));
            g_rank[0] = r99; g_rank[1] = r99;
            g_pfx[0] = 0u; g_pfx[1] = 0u;
        } else if (stage == 2) {
            g_s[0] = (float)(1.9705 / (((double)g_pfx[0] + 0.5) * g_kinv[0]));
            g_s[1] = (float)(1.0308 / (((double)g_pfx[1] + 0.5) * g_kinv[1]));
        }
    }
}

// ---------------- pass 3: 16-bit Cmat keys + plain-atomic hists ----------------
__global__ void k_cmat() {
    __shared__ unsigned sh[2][256];
    for (int i = threadIdx.x; i < 512; i += blockDim.x) ((unsigned*)sh)[i] = 0u;
    __syncthreads();
    float m0 = g_M[0], m1 = g_M[1], m2 = g_M[2];
    float m3 = g_M[3], m4 = g_M[4], m5 = g_M[5];
    float s0 = g_kscale[0], s1 = g_kscale[1];
    int tid = blockIdx.x * blockDim.x + threadIdx.x;
    int stride = gridDim.x * blockDim.x;
    for (int q = tid; q < NP / 4; q += stride) {
        int t = q << 2;
        float4 o0 = *(const float4*)(g_od + t);
        float4 o1 = *(const float4*)(g_od + NP + t);
        float4 o2 = *(const float4*)(g_od + 2 * NP + t);
        float a0[4] = {o0.x, o0.y, o0.z, o0.w};
        float a1[4] = {o1.x, o1.y, o1.z, o1.w};
        float a2[4] = {o2.x, o2.y, o2.z, o2.w};
        unsigned kA[4], kB[4];
#pragma unroll
        for (int j = 0; j < 4; j++) {
            float c0 = fmaf(a2[j], m2, fmaf(a1[j], m1, a0[j] * m0));
            float c1 = fmaf(a2[j], m5, fmaf(a1[j], m4, a0[j] * m3));
            float f0 = fminf(fmaxf(c0 * s0, 0.0f), 65535.0f);
            float f1 = fminf(fmaxf(c1 * s1, 0.0f), 65535.0f);
            kA[j] = (unsigned)f0; kB[j] = (unsigned)f1;
            padd(sh[0], kA[j] >> 8);
            padd(sh[1], kB[j] >> 8);
        }
        ushort4 va, vb;
        va.x = (unsigned short)kA[0]; va.y = (unsigned short)kA[1];
        va.z = (unsigned short)kA[2]; va.w = (unsigned short)kA[3];
        vb.x = (unsigned short)kB[0]; vb.y = (unsigned short)kB[1];
        vb.z = (unsigned short)kB[2]; vb.w = (unsigned short)kB[3];
        *(ushort4*)(g_keysA + t) = va;
        *(ushort4*)(g_keysB + t) = vb;
    }
    __syncthreads();
    for (int i = threadIdx.x; i < 256; i += blockDim.x) {
        if (sh[0][i]) atomicAdd(&g_hist[0][i], sh[0][i]);
        if (sh[1][i]) atomicAdd(&g_hist[1][i], sh[1][i]);
    }
}

// ---------------- pass 4: normalized output from fp32 OD cache ----------------
__global__ void k_out(float* __restrict__ out) {
    float m0 = g_M[0], m1 = g_M[1], m2 = g_M[2];
    float m3 = g_M[3], m4 = g_M[4], m5 = g_M[5];
    float s0 = g_s[0], s1 = g_s[1];
    int tid = blockIdx.x * blockDim.x + threadIdx.x;
    int stride = gridDim.x * blockDim.x;
    for (int q = tid; q < NP / 4; q += stride) {
        int t = q << 2;
        float4 o0 = *(const float4*)(g_od + t);
        float4 o1 = *(const float4*)(g_od + NP + t);
        float4 o2 = *(const float4*)(g_od + 2 * NP + t);
        float a0[4] = {o0.x, o0.y, o0.z, o0.w};
        float a1[4] = {o1.x, o1.y, o1.z, o1.w};
        float a2[4] = {o2.x, o2.y, o2.z, o2.w};
        float r0[4], r1[4], r2[4];
#pragma unroll
        for (int j = 0; j < 4; j++) {
            float c0 = fmaf(a2[j], m2, fmaf(a1[j], m1, a0[j] * m0)) * s0;
            float c1 = fmaf(a2[j], m5, fmaf(a1[j], m4, a0[j] * m3)) * s1;
            r0[j] = fminf(240.0f * fexp(-fmaf(0.5626f, c0, 0.2159f * c1)), 255.0f);
            r1[j] = fminf(240.0f * fexp(-fmaf(0.7201f, c0, 0.8012f * c1)), 255.0f);
            r2[j] = fminf(240.0f * fexp(-fmaf(0.4062f, c0, 0.5581f * c1)), 255.0f);
        }
        int b = t >> 18, hw = t & (HW - 1);
        float* o = out + (size_t)b * BSTRIDE + hw;
        *(float4*)(o)          = make_float4(r0[0], r0[1], r0[2], r0[3]);
        *(float4*)(o + HW)     = make_float4(r1[0], r1[1], r1[2], r1[3]);
        *(float4*)(o + 2 * HW) = make_float4(r2[0], r2[1], r2[2], r2[3]);
    }
}

// ---------------- launch (11 kernels; champion structure, no match_any hot path) ---
extern "C" void kernel_launch(void* const* d_in, const int* in_sizes, int n_in,
                              void* d_out, int out_size) {
    const float* x = (const float*)d_in[0];
    float* out = (float*)d_out;
    const int TB = 256;
    const int GB = 2048;

    k_stats<<<GB, TB>>>(x);
    k_finalize1<<<1, 1>>>();
    k_phi<<<GB, TB>>>();
    k_select<<<1, 64>>>(0);
    k_hist2<<<GB, TB>>>(0);
    k_select<<<1, 64>>>(1);
    k_cmat<<<GB, TB>>>();
    k_select<<<1, 64>>>(0);
    k_hist2<<<GB, TB>>>(1);
    k_select<<<1, 64>>>(2);
    k_out<<<GB, TB>>>(out);
}

// round 16
// speedup vs baseline: 1.5059x; 1.0115x over previous
#include <cuda_runtime.h>
#include <math.h>

#define NP 8388608          // 32*512*512 pixels
#define HW 262144           // 512*512
#define BSTRIDE 786432      // 3*HW
#define BETA_F 0.15f
#define ODMAX 5.4810        // > -log(1/240)
#define ODNEG 0.0646        // > log(256/240)

// uint16 fixed-point OD coding: q = rn(od*QS + QO); od = q*QINV + QNEG
#define QS   11800.0f
#define QO   763.0f
#define QINV (1.0f / 11800.0f)
#define QNEG (-763.0f / 11800.0f)
#define QBETA 2533u         // dq(q) >= 0.15  <=>  q >= 2533  (integer mask, exact everywhere)

// ---------------- device scratch (zero-initialized; every run restores invariants) ---
__device__ double   g_acc[11];             // 10 moments (fp32 mask) + n_q (quant mask)
__device__ double   g_emid[3], g_elarge[3];
__device__ float    g_emidf[3], g_elargef[3];
__device__ unsigned g_pfx[2];
__device__ long long g_rank[2];
__device__ float    g_M[6];
__device__ float    g_s[2];
__device__ float    g_kscale[2];
__device__ double   g_kinv[2];
__device__ unsigned g_hist[2][256];
__device__ unsigned short g_od[3ull * NP]; // OD cache uint16 fixed-point (48 MB)
__device__ unsigned short g_keysA[NP];
__device__ unsigned short g_keysB[NP];

// ---------------- helpers ----------------
// OD via MUFU: -log((v+1)/240) = ln2 * (log2(240) - log2(v+1)).
__device__ __forceinline__ float odf(float v) {
    return (7.9068905956085185f - __log2f(v + 1.0f)) * 0.6931471805599453f;
}
__device__ __forceinline__ unsigned odq(float od) {
    return __float2uint_rn(fmaf(od, QS, QO));
}
__device__ __forceinline__ float dq(unsigned q) {
    return fmaf((float)q, QINV, QNEG);
}

// FFMA-only exp(y). Cody-Waite reduction + degree-7 Taylor.
__device__ __forceinline__ float fexp(float y) {
    float z = y * 1.4426950408889634f;
    float n = rintf(z);
    float g = fmaf(n, -0.69314575f, y);
    g = fmaf(n, -1.4286068e-6f, g);
    float r = 1.9841270e-4f;
    r = fmaf(r, g, 1.3888889e-3f);
    r = fmaf(r, g, 8.3333333e-3f);
    r = fmaf(r, g, 4.1666667e-2f);
    r = fmaf(r, g, 1.6666667e-1f);
    r = fmaf(r, g, 0.5f);
    r = fmaf(r, g, 1.0f);
    r = fmaf(r, g, 1.0f);
    int ni = (int)n;
    ni = ni < -126 ? -126 : (ni > 127 ? 127 : ni);
    float s = __int_as_float((unsigned)(ni + 127) << 23);
    return r * s;
}

// deposit WITHOUT match_any: hot bin 0 aggregated via ballot+popc (one atomic/warp);
// all other digits use a plain per-thread shared atomic (spread -> low conflict).
__device__ __forceinline__ void padd(unsigned* row, unsigned digit) {
    unsigned zb = __ballot_sync(0xffffffffu, digit == 0u);
    if (digit == 0u) {
        if ((threadIdx.x & 31u) == (unsigned)(__ffs(zb) - 1))
            atomicAdd(&row[0], (unsigned)__popc(zb));
    } else {
        atomicAdd(&row[digit], 1u);
    }
}

// predicated warp-aggregated add (kept ONLY for k_hist2's rare deposits)
__device__ __forceinline__ void hadd(unsigned* row, unsigned digit, bool pred) {
    unsigned mm = __ballot_sync(0xffffffffu, pred);
    if (pred) {
        unsigned peers = __match_any_sync(mm, digit);
        int lane = threadIdx.x & 31;
        int leader = __ffs(peers) - 1;
        if (lane == leader) atomicAdd(&row[digit], (unsigned)__popc(peers));
    }
}

// ---------------- 3x3 symmetric Jacobi eigensolver (double) ----------------
__device__ void eig3(double A[3][3], double V[3][3], double w[3]) {
    for (int i = 0; i < 3; i++)
        for (int j = 0; j < 3; j++) V[i][j] = (i == j) ? 1.0 : 0.0;
    const int PQ[3][2] = {{0, 1}, {0, 2}, {1, 2}};
    for (int sweep = 0; sweep < 64; sweep++) {
        double off = A[0][1] * A[0][1] + A[0][2] * A[0][2] + A[1][2] * A[1][2];
        if (off < 1e-300) break;
        for (int r = 0; r < 3; r++) {
            int p = PQ[r][0], q = PQ[r][1];
            double apq = A[p][q];
            if (fabs(apq) < 1e-300) continue;
            double theta = (A[q][q] - A[p][p]) / (2.0 * apq);
            double tt = (theta >= 0.0 ? 1.0 : -1.0) / (fabs(theta) + sqrt(theta * theta + 1.0));
            double c = 1.0 / sqrt(tt * tt + 1.0);
            double s = tt * c;
            double app = A[p][p], aqq = A[q][q];
            A[p][p] = app - tt * apq;
            A[q][q] = aqq + tt * apq;
            A[p][q] = A[q][p] = 0.0;
            int k = 3 - p - q;
            double akp = A[k][p], akq = A[k][q];
            A[k][p] = A[p][k] = c * akp - s * akq;
            A[k][q] = A[q][k] = s * akp + c * akq;
            for (int k2 = 0; k2 < 3; k2++) {
                double vp = V[k2][p], vq = V[k2][q];
                V[k2][p] = c * vp - s * vq;
                V[k2][q] = s * vp + c * vq;
            }
        }
    }
    for (int i = 0; i < 3; i++) w[i] = A[i][i];
    for (int pass = 0; pass < 2; pass++)
        for (int i = 0; i < 2; i++)
            if (w[i] > w[i + 1]) {
                double tw = w[i]; w[i] = w[i + 1]; w[i + 1] = tw;
                for (int k = 0; k < 3; k++) {
                    double tv = V[k][i]; V[k][i] = V[k][i + 1]; V[k][i + 1] = tv;
                }
            }
}

// ---------------- pass 1: uint16 OD cache; cov from EXACT fp32 OD + fp32 mask ------
__global__ void k_stats(const float* __restrict__ x) {
    float a[11];
#pragma unroll
    for (int i = 0; i < 11; i++) a[i] = 0.0f;
    int tid = blockIdx.x * blockDim.x + threadIdx.x;
    int stride = gridDim.x * blockDim.x;
    for (int q = tid; q < NP / 8; q += stride) {
        int t = q << 3;
        int b = t >> 18, hw = t & (HW - 1);
        const float* p = x + (size_t)b * BSTRIDE + hw;
        float4 va0 = *(const float4*)(p);
        float4 vb0 = *(const float4*)(p + 4);
        float4 va1 = *(const float4*)(p + HW);
        float4 vb1 = *(const float4*)(p + HW + 4);
        float4 va2 = *(const float4*)(p + 2 * HW);
        float4 vb2 = *(const float4*)(p + 2 * HW + 4);
        float i0[8] = {va0.x, va0.y, va0.z, va0.w, vb0.x, vb0.y, vb0.z, vb0.w};
        float i1[8] = {va1.x, va1.y, va1.z, va1.w, vb1.x, vb1.y, vb1.z, vb1.w};
        float i2[8] = {va2.x, va2.y, va2.z, va2.w, vb2.x, vb2.y, vb2.z, vb2.w};
        float o0[8], o1[8], o2[8];
        unsigned q0[8], q1[8], q2[8];
#pragma unroll
        for (int j = 0; j < 8; j++) {
            o0[j] = odf(i0[j]); q0[j] = odq(o0[j]);
            o1[j] = odf(i1[j]); q1[j] = odq(o1[j]);
            o2[j] = odf(i2[j]); q2[j] = odq(o2[j]);
        }
        uint4 u0, u1, u2;
        u0.x = q0[0] | (q0[1] << 16); u0.y = q0[2] | (q0[3] << 16);
        u0.z = q0[4] | (q0[5] << 16); u0.w = q0[6] | (q0[7] << 16);
        u1.x = q1[0] | (q1[1] << 16); u1.y = q1[2] | (q1[3] << 16);
        u1.z = q1[4] | (q1[5] << 16); u1.w = q1[6] | (q1[7] << 16);
        u2.x = q2[0] | (q2[1] << 16); u2.y = q2[2] | (q2[3] << 16);
        u2.z = q2[4] | (q2[5] << 16); u2.w = q2[6] | (q2[7] << 16);
        *(uint4*)(g_od + t)          = u0;
        *(uint4*)(g_od + NP + t)     = u1;
        *(uint4*)(g_od + 2 * NP + t) = u2;
#pragma unroll
        for (int j = 0; j < 8; j++) {
            float d0 = o0[j], d1 = o1[j], d2 = o2[j];
            bool keep = !(d0 < BETA_F || d1 < BETA_F || d2 < BETA_F);  // EXACT fp32 mask
            if (keep) {
                a[0] += 1.0f; a[1] += d0; a[2] += d1; a[3] += d2;
                a[4] += d0 * d0; a[5] += d0 * d1; a[6] += d0 * d2;
                a[7] += d1 * d1; a[8] += d1 * d2; a[9] += d2 * d2;
            }
            if (q0[j] >= QBETA && q1[j] >= QBETA && q2[j] >= QBETA) a[10] += 1.0f;
        }
    }
    double d[11];
#pragma unroll
    for (int i = 0; i < 11; i++) d[i] = (double)a[i];
#pragma unroll
    for (int o = 16; o; o >>= 1)
#pragma unroll
        for (int i = 0; i < 11; i++) d[i] += __shfl_down_sync(0xffffffffu, d[i], o);
    __shared__ double sh[8][11];
    int lane = threadIdx.x & 31, w = threadIdx.x >> 5;
    if (lane == 0)
        for (int i = 0; i < 11; i++) sh[w][i] = d[i];
    __syncthreads();
    if (threadIdx.x == 0) {
        for (int ww = 1; ww < (int)(blockDim.x >> 5); ww++)
            for (int i = 0; i < 11; i++) sh[0][i] += sh[ww][i];
        for (int i = 0; i < 11; i++) atomicAdd(&g_acc[i], sh[0][i]);
    }
}

// ---------------- finalize stats: cov/eigvecs from exact moments; ranks from n_q ----
__global__ void k_finalize1() {
    double n = g_acc[0];
    double mu0 = g_acc[1] / n, mu1 = g_acc[2] / n, mu2 = g_acc[3] / n;
    double inv = 1.0 / (n - 1.0);
    double A[3][3];
    A[0][0] = (g_acc[4] - n * mu0 * mu0) * inv;
    A[0][1] = A[1][0] = (g_acc[5] - n * mu0 * mu1) * inv;
    A[0][2] = A[2][0] = (g_acc[6] - n * mu0 * mu2) * inv;
    A[1][1] = (g_acc[7] - n * mu1 * mu1) * inv;
    A[1][2] = A[2][1] = (g_acc[8] - n * mu1 * mu2) * inv;
    A[2][2] = (g_acc[9] - n * mu2 * mu2) * inv;
    double V[3][3], w[3];
    eig3(A, V, w);
    for (int i = 0; i < 3; i++) {
        g_emid[i] = V[i][1];  g_elarge[i] = V[i][2];
        g_emidf[i] = (float)V[i][1]; g_elargef[i] = (float)V[i][2];
    }
    double n_q = g_acc[10];
    long long nrej_q = (long long)NP - (long long)llrint(n_q);
    double nm1q = n_q - 1.0;
    g_rank[0] = nrej_q + llrint(0.01 * 1.0 * nm1q);
    g_rank[1] = nrej_q + llrint(0.01 * 99.0 * nm1q);
    g_pfx[0] = 0u; g_pfx[1] = 0u;
    for (int i = 0; i < 11; i++) g_acc[i] = 0.0;
}

// ---------------- pass 2: keys from uint16 cache; integer mask; padd deposits ------
__global__ void k_phi() {
    __shared__ unsigned sh[256];
    for (int i = threadIdx.x; i < 256; i += blockDim.x) sh[i] = 0u;
    __syncthreads();
    float e10 = g_emidf[0], e11 = g_emidf[1], e12 = g_emidf[2];
    float e20 = g_elargef[0], e21 = g_elargef[1], e22 = g_elargef[2];
    int tid = blockIdx.x * blockDim.x + threadIdx.x;
    int stride = gridDim.x * blockDim.x;
    for (int q = tid; q < NP / 8; q += stride) {
        int t = q << 3;
        uint4 u0 = *(const uint4*)(g_od + t);
        uint4 u1 = *(const uint4*)(g_od + NP + t);
        uint4 u2 = *(const uint4*)(g_od + 2 * NP + t);
        unsigned q0[8] = {u0.x & 0xFFFFu, u0.x >> 16, u0.y & 0xFFFFu, u0.y >> 16,
                          u0.z & 0xFFFFu, u0.z >> 16, u0.w & 0xFFFFu, u0.w >> 16};
        unsigned q1[8] = {u1.x & 0xFFFFu, u1.x >> 16, u1.y & 0xFFFFu, u1.y >> 16,
                          u1.z & 0xFFFFu, u1.z >> 16, u1.w & 0xFFFFu, u1.w >> 16};
        unsigned q2[8] = {u2.x & 0xFFFFu, u2.x >> 16, u2.y & 0xFFFFu, u2.y >> 16,
                          u2.z & 0xFFFFu, u2.z >> 16, u2.w & 0xFFFFu, u2.w >> 16};
        unsigned keys[8];
#pragma unroll
        for (int j = 0; j < 8; j++) {
            bool keep = (q0[j] >= QBETA) && (q1[j] >= QBETA) && (q2[j] >= QBETA);
            unsigned key = 0u;
            if (keep) {
                float a0 = dq(q0[j]), a1 = dq(q1[j]), a2 = dq(q2[j]);
                float t1 = fmaf(a2, e12, fmaf(a1, e11, a0 * e10));
                float t2 = fmaf(a2, e22, fmaf(a1, e21, a0 * e20));
                float s = fabsf(t1) + fabsf(t2);
                float p = copysignf(1.0f - __fdividef(t1, s), t2);  // diamond angle
                float kf = fmaf(p, 16383.75f, 32767.5f);
                kf = fminf(fmaxf(kf, 0.0f), 65535.0f);
                key = (unsigned)kf;
            }
            keys[j] = key;
            padd(sh, key >> 8);
        }
        uint4 kv;
        kv.x = keys[0] | (keys[1] << 16); kv.y = keys[2] | (keys[3] << 16);
        kv.z = keys[4] | (keys[5] << 16); kv.w = keys[6] | (keys[7] << 16);
        *(uint4*)(g_keysA + t) = kv;
    }
    __syncthreads();
    for (int i = threadIdx.x; i < 256; i += blockDim.x) {
        unsigned c = sh[i];
        if (c) { atomicAdd(&g_hist[0][i], c); atomicAdd(&g_hist[1][i], c); }
    }
}

// ---------------- low-byte histogram pass over 16-bit keys (rare deposits) ---------
__global__ void k_hist2(int useB) {
    __shared__ unsigned sh[2][256];
    for (int i = threadIdx.x; i < 512; i += blockDim.x) ((unsigned*)sh)[i] = 0u;
    __syncthreads();
    unsigned p0 = g_pfx[0], p1 = g_pfx[1];
    int tid = blockIdx.x * blockDim.x + threadIdx.x;
    int stride = gridDim.x * blockDim.x;
    for (int q = tid; q < NP / 8; q += stride) {
        uint4 va = ((const uint4*)g_keysA)[q];
        unsigned ka[8] = {va.x & 0xFFFFu, va.x >> 16, va.y & 0xFFFFu, va.y >> 16,
                          va.z & 0xFFFFu, va.z >> 16, va.w & 0xFFFFu, va.w >> 16};
        if (useB) {
            uint4 vb = ((const uint4*)g_keysB)[q];
            unsigned kb[8] = {vb.x & 0xFFFFu, vb.x >> 16, vb.y & 0xFFFFu, vb.y >> 16,
                              vb.z & 0xFFFFu, vb.z >> 16, vb.w & 0xFFFFu, vb.w >> 16};
#pragma unroll
            for (int j = 0; j < 8; j++) {
                hadd(sh[0], ka[j] & 255u, (ka[j] >> 8) == p0);
                hadd(sh[1], kb[j] & 255u, (kb[j] >> 8) == p1);
            }
        } else {
#pragma unroll
            for (int j = 0; j < 8; j++) {
                hadd(sh[0], ka[j] & 255u, (ka[j] >> 8) == p0);
                hadd(sh[1], ka[j] & 255u, (ka[j] >> 8) == p1);
            }
        }
    }
    __syncthreads();
    for (int i = threadIdx.x; i < 256; i += blockDim.x) {
        if (sh[0][i]) atomicAdd(&g_hist[0][i], sh[0][i]);
        if (sh[1][i]) atomicAdd(&g_hist[1][i], sh[1][i]);
    }
}

// ---------------- select + staged finalize ----------------
__global__ void k_select(int stage) {
    int tsel = threadIdx.x >> 5;
    int lane = threadIdx.x & 31;
    long long r = g_rank[tsel];
    unsigned run = 0u; int found = -1; unsigned before = 0u;
    for (int base = 0; base < 256; base += 32) {
        unsigned c = g_hist[tsel][base + lane];
        unsigned inc = c;
#pragma unroll
        for (int o = 1; o < 32; o <<= 1) {
            unsigned v = __shfl_up_sync(0xffffffffu, inc, o);
            if (lane >= o) inc += v;
        }
        unsigned tot = __shfl_sync(0xffffffffu, inc, 31);
        if (found < 0) {
            long long excl = (long long)run + (long long)(inc - c);
            long long cum  = (long long)run + (long long)inc;
            bool hit = (excl <= r) && (cum > r);
            unsigned hm = __ballot_sync(0xffffffffu, hit);
            if (hm) {
                int hl = __ffs(hm) - 1;
                found = base + hl;
                before = run + __shfl_sync(0xffffffffu, inc - c, hl);
            }
        }
        run += tot;
        g_hist[tsel][base + lane] = 0u;
    }
    if (lane == 0) {
        g_pfx[tsel] = (g_pfx[tsel] << 8) | (unsigned)found;
        g_rank[tsel] = r - (long long)before;
    }
    __syncthreads();
    if (threadIdx.x == 0) {
        if (stage == 1) {
            double ph[2];
            for (int t = 0; t < 2; t++) {
                double p = ((double)g_pfx[t] + 0.5) / 16383.75 - 2.0;
                double ap = fabs(p);
                double xx = 1.0 - ap;
                double yy = (1.0 - fabs(1.0 - ap)); yy = (p < 0.0) ? -yy : yy;
                ph[t] = atan2(yy, xx);
            }
            double vMin[3], vMax[3];
            double cmin = cos(ph[0]), smin = sin(ph[0]);
            double cmax = cos(ph[1]), smax = sin(ph[1]);
            for (int i = 0; i < 3; i++) {
                vMin[i] = cmin * g_emid[i] + smin * g_elarge[i];
                vMax[i] = cmax * g_emid[i] + smax * g_elarge[i];
            }
            double h1[3], h2[3];
            if (vMin[0] > vMax[0]) {
                for (int i = 0; i < 3; i++) { h1[i] = vMin[i]; h2[i] = vMax[i]; }
            } else {
                for (int i = 0; i < 3; i++) { h1[i] = vMax[i]; h2[i] = vMin[i]; }
            }
            double a = h1[0]*h1[0] + h1[1]*h1[1] + h1[2]*h1[2];
            double b = h1[0]*h2[0] + h1[1]*h2[1] + h1[2]*h2[2];
            double d = h2[0]*h2[0] + h2[1]*h2[1] + h2[2]*h2[2];
            double det = a * d - b * b;
            double M[6];
            for (int i = 0; i < 3; i++) {
                M[i]     = (d * h1[i] - b * h2[i]) / det;
                M[3 + i] = (a * h2[i] - b * h1[i]) / det;
            }
            for (int i = 0; i < 6; i++) g_M[i] = (float)M[i];
            for (int t = 0; t < 2; t++) {
                double R = 0.0;
                for (int i = 0; i < 3; i++) {
                    double m = M[3 * t + i];
                    R += (m > 0.0) ? m * ODMAX : -m * ODNEG;
                }
                R = R * 1.001 + 1e-6;
                g_kscale[t] = (float)(65535.0 / R);
                g_kinv[t] = R / 65535.0;
            }
            long long r99 = llrint(0.01 * 99.0 * (double)(NP - 1));
            g_rank[0] = r99; g_rank[1] = r99;
            g_pfx[0] = 0u; g_pfx[1] = 0u;
        } else if (stage == 2) {
            g_s[0] = (float)(1.9705 / (((double)g_pfx[0] + 0.5) * g_kinv[0]));
            g_s[1] = (float)(1.0308 / (((double)g_pfx[1] + 0.5) * g_kinv[1]));
        }
    }
}

// ---------------- pass 3: 16-bit Cmat keys from uint16 cache; padd deposits --------
__global__ void k_cmat() {
    __shared__ unsigned sh[2][256];
    for (int i = threadIdx.x; i < 512; i += blockDim.x) ((unsigned*)sh)[i] = 0u;
    __syncthreads();
    float m0 = g_M[0], m1 = g_M[1], m2 = g_M[2];
    float m3 = g_M[3], m4 = g_M[4], m5 = g_M[5];
    float s0 = g_kscale[0], s1 = g_kscale[1];
    int tid = blockIdx.x * blockDim.x + threadIdx.x;
    int stride = gridDim.x * blockDim.x;
    for (int q = tid; q < NP / 8; q += stride) {
        int t = q << 3;
        uint4 u0 = *(const uint4*)(g_od + t);
        uint4 u1 = *(const uint4*)(g_od + NP + t);
        uint4 u2 = *(const uint4*)(g_od + 2 * NP + t);
        unsigned q0[8] = {u0.x & 0xFFFFu, u0.x >> 16, u0.y & 0xFFFFu, u0.y >> 16,
                          u0.z & 0xFFFFu, u0.z >> 16, u0.w & 0xFFFFu, u0.w >> 16};
        unsigned q1[8] = {u1.x & 0xFFFFu, u1.x >> 16, u1.y & 0xFFFFu, u1.y >> 16,
                          u1.z & 0xFFFFu, u1.z >> 16, u1.w & 0xFFFFu, u1.w >> 16};
        unsigned q2[8] = {u2.x & 0xFFFFu, u2.x >> 16, u2.y & 0xFFFFu, u2.y >> 16,
                          u2.z & 0xFFFFu, u2.z >> 16, u2.w & 0xFFFFu, u2.w >> 16};
        unsigned kA[8], kB[8];
#pragma unroll
        for (int j = 0; j < 8; j++) {
            float a0 = dq(q0[j]), a1 = dq(q1[j]), a2 = dq(q2[j]);
            float c0 = fmaf(a2, m2, fmaf(a1, m1, a0 * m0));
            float c1 = fmaf(a2, m5, fmaf(a1, m4, a0 * m3));
            float f0 = fminf(fmaxf(c0 * s0, 0.0f), 65535.0f);
            float f1 = fminf(fmaxf(c1 * s1, 0.0f), 65535.0f);
            kA[j] = (unsigned)f0; kB[j] = (unsigned)f1;
            padd(sh[0], kA[j] >> 8);
            padd(sh[1], kB[j] >> 8);
        }
        uint4 va, vb;
        va.x = kA[0] | (kA[1] << 16); va.y = kA[2] | (kA[3] << 16);
        va.z = kA[4] | (kA[5] << 16); va.w = kA[6] | (kA[7] << 16);
        vb.x = kB[0] | (kB[1] << 16); vb.y = kB[2] | (kB[3] << 16);
        vb.z = kB[4] | (kB[5] << 16); vb.w = kB[6] | (kB[7] << 16);
        *(uint4*)(g_keysA + t) = va;
        *(uint4*)(g_keysB + t) = vb;
    }
    __syncthreads();
    for (int i = threadIdx.x; i < 256; i += blockDim.x) {
        if (sh[0][i]) atomicAdd(&g_hist[0][i], sh[0][i]);
        if (sh[1][i]) atomicAdd(&g_hist[1][i], sh[1][i]);
    }
}

// ---------------- pass 4: normalized output from uint16 OD cache ----------------
__global__ void k_out(float* __restrict__ out) {
    float m0 = g_M[0], m1 = g_M[1], m2 = g_M[2];
    float m3 = g_M[3], m4 = g_M[4], m5 = g_M[5];
    float s0 = g_s[0], s1 = g_s[1];
    int tid = blockIdx.x * blockDim.x + threadIdx.x;
    int stride = gridDim.x * blockDim.x;
    for (int q = tid; q < NP / 8; q += stride) {
        int t = q << 3;
        uint4 u0 = *(const uint4*)(g_od + t);
        uint4 u1 = *(const uint4*)(g_od + NP + t);
        uint4 u2 = *(const uint4*)(g_od + 2 * NP + t);
        unsigned q0[8] = {u0.x & 0xFFFFu, u0.x >> 16, u0.y & 0xFFFFu, u0.y >> 16,
                          u0.z & 0xFFFFu, u0.z >> 16, u0.w & 0xFFFFu, u0.w >> 16};
        unsigned q1[8] = {u1.x & 0xFFFFu, u1.x >> 16, u1.y & 0xFFFFu, u1.y >> 16,
                          u1.z & 0xFFFFu, u1.z >> 16, u1.w & 0xFFFFu, u1.w >> 16};
        unsigned q2[8] = {u2.x & 0xFFFFu, u2.x >> 16, u2.y & 0xFFFFu, u2.y >> 16,
                          u2.z & 0xFFFFu, u2.z >> 16, u2.w & 0xFFFFu, u2.w >> 16};
        float r0[8], r1[8], r2[8];
#pragma unroll
        for (int j = 0; j < 8; j++) {
            float a0 = dq(q0[j]), a1 = dq(q1[j]), a2 = dq(q2[j]);
            float c0 = fmaf(a2, m2, fmaf(a1, m1, a0 * m0)) * s0;
            float c1 = fmaf(a2, m5, fmaf(a1, m4, a0 * m3)) * s1;
            r0[j] = fminf(240.0f * fexp(-fmaf(0.5626f, c0, 0.2159f * c1)), 255.0f);
            r1[j] = fminf(240.0f * fexp(-fmaf(0.7201f, c0, 0.8012f * c1)), 255.0f);
            r2[j] = fminf(240.0f * fexp(-fmaf(0.4062f, c0, 0.5581f * c1)), 255.0f);
        }
        int b = t >> 18, hw = t & (HW - 1);
        float* o = out + (size_t)b * BSTRIDE + hw;
        *(float4*)(o)              = make_float4(r0[0], r0[1], r0[2], r0[3]);
        *(float4*)(o + 4)          = make_float4(r0[4], r0[5], r0[6], r0[7]);
        *(float4*)(o + HW)         = make_float4(r1[0], r1[1], r1[2], r1[3]);
        *(float4*)(o + HW + 4)     = make_float4(r1[4], r1[5], r1[6], r1[7]);
        *(float4*)(o + 2 * HW)     = make_float4(r2[0], r2[1], r2[2], r2[3]);
        *(float4*)(o + 2 * HW + 4) = make_float4(r2[4], r2[5], r2[6], r2[7]);
    }
}

// ---------------- launch (11 kernels; R15 deposits + R13 uint16 hybrid) ------------
extern "C" void kernel_launch(void* const* d_in, const int* in_sizes, int n_in,
                              void* d_out, int out_size) {
    const float* x = (const float*)d_in[0];
    float* out = (float*)d_out;
    const int TB = 256;
    const int GB = 2048;

    k_stats<<<GB, TB>>>(x);
    k_finalize1<<<1, 1>>>();
    k_phi<<<GB, TB>>>();
    k_select<<<1, 64>>>(0);
    k_hist2<<<GB, TB>>>(0);
    k_select<<<1, 64>>>(1);
    k_cmat<<<GB, TB>>>();
    k_select<<<1, 64>>>(0);
    k_hist2<<<GB, TB>>>(1);
    k_select<<<1, 64>>>(2);
    k_out<<<GB, TB>>>(out);
}